// round 1
// baseline (speedup 1.0000x reference)
#include <cuda_runtime.h>
#include <cstdint>

#define NPTS   16384
#define NGRP   (NPTS/2)     // target point-pairs (f32x2 groups)
#define QT     16           // query tiles per direction (1024 rows each)
#define SPLITS 9            // target-range splits per query tile
#define RPT    4            // query rows per thread
#define TPB    256

// Packed target table: [dir][2*g] = (-2x0,-2x1,-2y0,-2y1), [2*g+1] = (-2z0,-2z1,s0,s1)
__device__ float4       g_tpack[2][NPTS];
// Per-row running min (order-preserving encoded float), merged across splits via atomicMin
__device__ unsigned int g_rowmin[2][NPTS];

// ---- order-preserving float<->uint encode (safe for negative values too) ----
static __device__ __forceinline__ unsigned enc_f(float f) {
    unsigned u = __float_as_uint(f);
    return (u & 0x80000000u) ? ~u : (u | 0x80000000u);
}
static __device__ __forceinline__ float dec_f(unsigned u) {
    unsigned b = (u & 0x80000000u) ? (u & 0x7fffffffu) : ~u;
    return __uint_as_float(b);
}

// ---- packed f32x2 helpers (Blackwell FFMA2 path — not emitted by ptxas from C++) ----
static __device__ __forceinline__ unsigned long long pack2(float x) {
    unsigned long long r;
    asm("mov.b64 %0, {%1, %1};" : "=l"(r) : "f"(x));
    return r;
}
static __device__ __forceinline__ unsigned long long fma2(
    unsigned long long a, unsigned long long b, unsigned long long c) {
    unsigned long long d;
    asm("fma.rn.f32x2 %0, %1, %2, %3;" : "=l"(d) : "l"(a), "l"(b), "l"(c));
    return d;
}
static __device__ __forceinline__ void unpack2(unsigned long long v, float& lo, float& hi) {
    asm("mov.b64 {%0, %1}, %2;" : "=f"(lo), "=f"(hi) : "l"(v));
}

// ============================================================================
// Kernel 1: build packed target tables + reset row-min state (graph-replay safe)
// ============================================================================
__global__ void chamfer_prep(const float* __restrict__ adv, const float* __restrict__ ori) {
    int i = blockIdx.x * blockDim.x + threadIdx.x;
    if (i >= NPTS) return;
#pragma unroll
    for (int d = 0; d < 2; d++) {
        // dir 0: queries=adv, targets=ori ; dir 1: queries=ori, targets=adv
        const float* src = d ? adv : ori;
        float x = src[3 * i + 0];
        float y = src[3 * i + 1];
        float z = src[3 * i + 2];
        float s = x * x + y * y + z * z;
        int g = i >> 1, h = i & 1;
        float* base = reinterpret_cast<float*>(&g_tpack[d][2 * g]);
        base[0 + h] = -2.0f * x;
        base[2 + h] = -2.0f * y;
        base[4 + h] = -2.0f * z;
        base[6 + h] = s;
        g_rowmin[d][i] = 0xFF800000u;  // enc(+inf)
    }
}

// ============================================================================
// Kernel 2: main pairwise sweep. Each block: (dir, query tile, target split).
// Thread holds RPT query rows in registers; inner loop streams packed target
// pairs (uniform loads -> L1 broadcast) and runs 3x FFMA2 + 2x FMNMX per pair.
// ============================================================================
__global__ void __launch_bounds__(TPB, 2)
chamfer_main(const float* __restrict__ adv, const float* __restrict__ ori) {
    int b   = blockIdx.x;
    int dir = b / (QT * SPLITS);
    int rem = b % (QT * SPLITS);
    int qt  = rem / SPLITS;
    int sp  = rem % SPLITS;

    const float* qsrc = dir ? ori : adv;
    int row0 = qt * (TPB * RPT) + threadIdx.x * RPT;

    unsigned long long axx[RPT], ayy[RPT], azz[RPT];
    float asq[RPT], m0[RPT], m1[RPT];
#pragma unroll
    for (int r = 0; r < RPT; r++) {
        float x = qsrc[3 * (row0 + r) + 0];
        float y = qsrc[3 * (row0 + r) + 1];
        float z = qsrc[3 * (row0 + r) + 2];
        axx[r] = pack2(x);
        ayy[r] = pack2(y);
        azz[r] = pack2(z);
        asq[r] = x * x + y * y + z * z;
        m0[r] = __int_as_float(0x7F800000);  // +inf
        m1[r] = __int_as_float(0x7F800000);
    }

    int gs = (sp * NGRP) / SPLITS;
    int ge = ((sp + 1) * NGRP) / SPLITS;
    const ulonglong2* tp = reinterpret_cast<const ulonglong2*>(&g_tpack[dir][0]);

#pragma unroll 4
    for (int g = gs; g < ge; g++) {
        ulonglong2 p = tp[2 * g];      // (xx pair, yy pair)
        ulonglong2 q = tp[2 * g + 1];  // (zz pair, ss pair)
#pragma unroll
        for (int r = 0; r < RPT; r++) {
            unsigned long long dd =
                fma2(axx[r], p.x, fma2(ayy[r], p.y, fma2(azz[r], q.x, q.y)));
            float d0, d1;
            unpack2(dd, d0, d1);
            m0[r] = fminf(m0[r], d0);
            m1[r] = fminf(m1[r], d1);
        }
    }

#pragma unroll
    for (int r = 0; r < RPT; r++) {
        float m = fminf(m0[r], m1[r]) + asq[r];
        atomicMin(&g_rowmin[dir][row0 + r], enc_f(m));
    }
}

// ============================================================================
// Kernel 3: reduce both directions' row-mins to the scalar chamfer loss.
// mean0 + mean1 == (sum of all 2*NPTS mins) / NPTS  (equal counts).
// ============================================================================
__global__ void chamfer_reduce(float* __restrict__ out) {
    __shared__ float sh[256];
    const unsigned* rm = reinterpret_cast<const unsigned*>(g_rowmin);
    float s = 0.0f;
    for (int i = threadIdx.x; i < 2 * NPTS; i += 256) s += dec_f(rm[i]);
    sh[threadIdx.x] = s;
    __syncthreads();
    for (int k = 128; k > 0; k >>= 1) {
        if (threadIdx.x < k) sh[threadIdx.x] += sh[threadIdx.x + k];
        __syncthreads();
    }
    if (threadIdx.x == 0) out[0] = sh[0] / (float)NPTS;
}

extern "C" void kernel_launch(void* const* d_in, const int* in_sizes, int n_in,
                              void* d_out, int out_size) {
    const float* adv = (const float*)d_in[0];
    const float* ori = (const float*)d_in[1];
    chamfer_prep<<<(NPTS + 255) / 256, 256>>>(adv, ori);
    chamfer_main<<<2 * QT * SPLITS, TPB>>>(adv, ori);
    chamfer_reduce<<<1, 256>>>((float*)d_out);
}

// round 3
// speedup vs baseline: 1.1397x; 1.1397x over previous
#include <cuda_runtime.h>
#include <cstdint>

#define NPTS    16384
#define TPB     256
#define QPB     256                 // queries per block (8 warps x 32)
#define QTILES  (NPTS/QPB)          // 64
#define TSPLIT  32
#define SLICE   (NPTS/TSPLIT)       // 512 targets per block slice
#define DIRBLKS (QTILES*TSPLIT)     // 2048 blocks per direction

// Prep tables (per direction). Slot vectors:
//  qI  (query,  MMA1-A, k-interleaved pairs): (xh,yl, yh,zl, zh,0, xl,0)
//  tB1 (target, MMA1-B, k-interleaved pairs): (xh,yh, yh,zh, zh,0, xh,0)
//  tLo (target, MMA2-B):                      (xl,yl,zl,0)
//  tQ2: (-tsq/2) pairs for MMA C-init
__device__ float    g_qI [2][NPTS][8];
__device__ float    g_tB1[2][NPTS][8];
__device__ float    g_tLo[2][NPTS][4];
__device__ float2   g_tQ2[2][NPTS/2];
__device__ float    g_qsq[2][NPTS];
__device__ unsigned g_rowmin[2][NPTS];

// ---- order-preserving float<->uint encode ----
static __device__ __forceinline__ unsigned enc_f(float f) {
    unsigned u = __float_as_uint(f);
    return (u & 0x80000000u) ? ~u : (u | 0x80000000u);
}
static __device__ __forceinline__ float dec_f(unsigned u) {
    unsigned b = (u & 0x80000000u) ? (u & 0x7fffffffu) : ~u;
    return __uint_as_float(b);
}

static __device__ __forceinline__ float tf32r(float x) {
    unsigned u;
    asm("cvt.rna.tf32.f32 %0, %1;" : "=r"(u) : "f"(x));
    return __uint_as_float(u);
}

// m16n8k8 tf32 MMA, fp32 accum. A row-major, B col-major.
#define MMA_TF32(d0,d1,d2,d3, a0,a1,a2,a3, b0,b1, c0,c1,c2,c3)                      \
    asm("mma.sync.aligned.m16n8k8.row.col.f32.tf32.tf32.f32 "                       \
        "{%0,%1,%2,%3}, {%4,%5,%6,%7}, {%8,%9}, {%10,%11,%12,%13};"                 \
        : "=f"(d0), "=f"(d1), "=f"(d2), "=f"(d3)                                    \
        : "r"(__float_as_uint(a0)), "r"(__float_as_uint(a1)),                       \
          "r"(__float_as_uint(a2)), "r"(__float_as_uint(a3)),                       \
          "r"(__float_as_uint(b0)), "r"(__float_as_uint(b1)),                       \
          "f"(c0), "f"(c1), "f"(c2), "f"(c3))

// ============================================================================
// Kernel 1: build fragment tables for both directions + reset row-min state.
// dir 0: queries = adv, targets = ori.  dir 1: swapped.
// ============================================================================
__global__ void chamfer_prep(const float* __restrict__ adv, const float* __restrict__ ori) {
    int i = blockIdx.x * blockDim.x + threadIdx.x;
    if (i >= NPTS) return;
#pragma unroll
    for (int p = 0; p < 2; p++) {
        const float* src = p ? ori : adv;
        float x = src[3 * i + 0];
        float y = src[3 * i + 1];
        float z = src[3 * i + 2];
        float xh = tf32r(x), yh = tf32r(y), zh = tf32r(z);
        float xl = tf32r(x - xh), yl = tf32r(y - yh), zl = tf32r(z - zh);
        float sq = x * x + y * y + z * z;

        int qd = p;        // this point is the query for dir p
        int td = 1 - p;    // and the target for the other dir

        float* q = &g_qI[qd][i][0];
        q[0] = xh; q[1] = yl; q[2] = yh; q[3] = zl;
        q[4] = zh; q[5] = 0.f; q[6] = xl; q[7] = 0.f;
        g_qsq[qd][i] = sq;
        g_rowmin[qd][i] = 0xFF800000u;  // enc(+inf)

        float* t = &g_tB1[td][i][0];
        t[0] = xh; t[1] = yh; t[2] = yh; t[3] = zh;
        t[4] = zh; t[5] = 0.f; t[6] = xh; t[7] = 0.f;
        float* l = &g_tLo[td][i][0];
        l[0] = xl; l[1] = yl; l[2] = zl; l[3] = 0.f;
        reinterpret_cast<float*>(&g_tQ2[td][i >> 1])[i & 1] = -0.5f * sq;
    }
}

// ============================================================================
// Kernel 2: main sweep. Block = (dir, 256-query tile, 512-target slice).
// Warp owns 32 queries (two m16 A-sets); inner loop: 8 targets/chunk,
// 2 tf32 MMAs per A-set (fp32-split), max-tracking epilogue.
// D = q.t - tsq/2  ->  min_j sqdist = qsq - 2*max_j D.
// ============================================================================
__global__ void __launch_bounds__(TPB)
chamfer_main() {
    __shared__ float  sB1[SLICE][8];
    __shared__ float  sLo[SLICE][4];
    __shared__ float2 sQ2[SLICE / 2];

    int b   = blockIdx.x;
    int dir = b >= DIRBLKS;
    int rem = b - dir * DIRBLKS;
    int qt  = rem / TSPLIT;
    int sp  = rem % TSPLIT;
    int tbase = sp * SLICE;

    // ---- stage target slice into smem (vectorized copy from prep tables) ----
    {
        const float4* s1 = reinterpret_cast<const float4*>(&g_tB1[dir][tbase][0]);
        float4*       d1 = reinterpret_cast<float4*>(&sB1[0][0]);
        for (int k = threadIdx.x; k < SLICE * 2; k += TPB) d1[k] = s1[k];
        const float4* s2 = reinterpret_cast<const float4*>(&g_tLo[dir][tbase][0]);
        float4*       d2 = reinterpret_cast<float4*>(&sLo[0][0]);
        for (int k = threadIdx.x; k < SLICE; k += TPB) d2[k] = s2[k];
        const float4* s3 = reinterpret_cast<const float4*>(&g_tQ2[dir][tbase >> 1]);
        float4*       d3 = reinterpret_cast<float4*>(&sQ2[0]);
        for (int k = threadIdx.x; k < SLICE / 4; k += TPB) d3[k] = s3[k];
    }

    int lane = threadIdx.x & 31;
    int warp = threadIdx.x >> 5;
    int gid  = lane >> 2;   // 0..7
    int tig  = lane & 3;    // 0..3

    int r0 = qt * QPB + warp * 32 + gid;  // A-set 0: rows r0, r0+8
    int r1 = r0 + 16;                     // A-set 1: rows r1, r1+8

    // ---- A fragments (loaded once; LDG.64 from interleaved tables) ----
    float2 p;
    p = *reinterpret_cast<const float2*>(&g_qI[dir][r0][2 * tig]);     float a10 = p.x, a12 = p.y;
    p = *reinterpret_cast<const float2*>(&g_qI[dir][r0 + 8][2 * tig]); float a11 = p.x, a13 = p.y;
    p = *reinterpret_cast<const float2*>(&g_qI[dir][r1][2 * tig]);     float a20 = p.x, a22 = p.y;
    p = *reinterpret_cast<const float2*>(&g_qI[dir][r1 + 8][2 * tig]); float a21 = p.x, a23 = p.y;
    // MMA2-A = hi coords only (slots k0..2); slot k3 of MMA1-A is x_lo -> mask
    float a10p = (tig < 3) ? a10 : 0.f;
    float a11p = (tig < 3) ? a11 : 0.f;
    float a20p = (tig < 3) ? a20 : 0.f;
    float a21p = (tig < 3) ? a21 : 0.f;
    const float zero = 0.f;

    float ninf = __int_as_float(0xFF800000);
    float mx00 = ninf, mx01 = ninf, mx10 = ninf, mx11 = ninf;

    __syncthreads();

#pragma unroll 4
    for (int j = 0; j < SLICE; j += 8) {
        int jj = j + gid;
        float2 b01 = *reinterpret_cast<const float2*>(&sB1[jj][2 * tig]);
        float  bl  = sLo[jj][tig];
        float2 ci  = sQ2[(j >> 1) + tig];

        float d0, d1, d2, d3;
        // ---- A-set 0 ----
        MMA_TF32(d0, d1, d2, d3, a10, a11, a12, a13, b01.x, b01.y, ci.x, ci.y, ci.x, ci.y);
        MMA_TF32(d0, d1, d2, d3, a10p, a11p, zero, zero, bl, zero, d0, d1, d2, d3);
        mx00 = fmaxf(mx00, fmaxf(d0, d1));
        mx01 = fmaxf(mx01, fmaxf(d2, d3));
        // ---- A-set 1 ----
        MMA_TF32(d0, d1, d2, d3, a20, a21, a22, a23, b01.x, b01.y, ci.x, ci.y, ci.x, ci.y);
        MMA_TF32(d0, d1, d2, d3, a20p, a21p, zero, zero, bl, zero, d0, d1, d2, d3);
        mx10 = fmaxf(mx10, fmaxf(d0, d1));
        mx11 = fmaxf(mx11, fmaxf(d2, d3));
    }

    // ---- fold: max across the 4 tig lanes holding the same row, then atomicMin ----
    unsigned m = 0xffffffffu;
#pragma unroll
    for (int s = 1; s <= 2; s <<= 1) {
        mx00 = fmaxf(mx00, __shfl_xor_sync(m, mx00, s));
        mx01 = fmaxf(mx01, __shfl_xor_sync(m, mx01, s));
        mx10 = fmaxf(mx10, __shfl_xor_sync(m, mx10, s));
        mx11 = fmaxf(mx11, __shfl_xor_sync(m, mx11, s));
    }
    if (tig == 0) {
        float c0 = fmaf(-2.f, mx00, g_qsq[dir][r0]);
        float c1 = fmaf(-2.f, mx01, g_qsq[dir][r0 + 8]);
        float c2 = fmaf(-2.f, mx10, g_qsq[dir][r1]);
        float c3 = fmaf(-2.f, mx11, g_qsq[dir][r1 + 8]);
        atomicMin(&g_rowmin[dir][r0],      enc_f(c0));
        atomicMin(&g_rowmin[dir][r0 + 8],  enc_f(c1));
        atomicMin(&g_rowmin[dir][r1],      enc_f(c2));
        atomicMin(&g_rowmin[dir][r1 + 8],  enc_f(c3));
    }
}

// ============================================================================
// Kernel 3: reduce both directions' row-mins to the scalar chamfer loss.
// ============================================================================
__global__ void chamfer_reduce(float* __restrict__ out) {
    __shared__ float sh[256];
    const unsigned* rm = reinterpret_cast<const unsigned*>(g_rowmin);
    float s = 0.0f;
    for (int i = threadIdx.x; i < 2 * NPTS; i += 256) s += dec_f(rm[i]);
    sh[threadIdx.x] = s;
    __syncthreads();
    for (int k = 128; k > 0; k >>= 1) {
        if (threadIdx.x < k) sh[threadIdx.x] += sh[threadIdx.x + k];
        __syncthreads();
    }
    if (threadIdx.x == 0) out[0] = sh[0] / (float)NPTS;
}

extern "C" void kernel_launch(void* const* d_in, const int* in_sizes, int n_in,
                              void* d_out, int out_size) {
    const float* adv = (const float*)d_in[0];
    const float* ori = (const float*)d_in[1];
    chamfer_prep<<<NPTS / 256, 256>>>(adv, ori);
    chamfer_main<<<2 * DIRBLKS, TPB>>>();
    chamfer_reduce<<<1, 256>>>((float*)d_out);
}

// round 4
// speedup vs baseline: 1.8002x; 1.5795x over previous
#include <cuda_runtime.h>
#include <cuda_fp16.h>
#include <cstdint>

#define NPTS    16384
#define TPB     256
#define QPB     256                  // queries per block (8 warps x 32 rows)
#define QT      (NPTS/QPB)           // 64 query tiles per direction
#define TSPLIT  16
#define SLICE   (NPTS/TSPLIT)        // 1024 targets per block
#define DIRBLKS (QT*TSPLIT)          // 1024 blocks per direction
#define REDA    (2*NPTS/TPB)         // 128 blocks in first reduction

// Per-(dir,slice) partial min-sqdists; fully rewritten every replay (no init needed).
__device__ float g_part[2][TSPLIT][NPTS];
__device__ float g_bsum[REDA];

static __device__ __forceinline__ unsigned pkh2(__half lo, __half hi) {
    __half2 h = __halves2half2(lo, hi);
    return *reinterpret_cast<unsigned*>(&h);
}

// m16n8k16 fp16 MMA, fp32 accumulate. A row-major, B col-major.
#define MMA_F16(d0,d1,d2,d3, a0,a1,a2,a3, b0,b1, c0,c1,c2,c3)                       \
    asm("mma.sync.aligned.m16n8k16.row.col.f32.f16.f16.f32 "                        \
        "{%0,%1,%2,%3}, {%4,%5,%6,%7}, {%8,%9}, {%10,%11,%12,%13};"                 \
        : "=f"(d0), "=f"(d1), "=f"(d2), "=f"(d3)                                    \
        : "r"(a0), "r"(a1), "r"(a2), "r"(a3), "r"(b0), "r"(b1),                     \
          "f"(c0), "f"(c1), "f"(c2), "f"(c3))

// ============================================================================
// Main kernel. Block = (dir, 256-query tile, 1024-target slice).
// Stages fp16-split fragments for its targets+queries in smem, then runs the
// MMA sweep: per 8-target chunk per warp, ONE m16n8k16 HMMA per 16-query set.
// K-slot layout (9 used):  A = (xh,yh,zh, xl,yl,zl, xh,yh,zh, 0...)
//                          B = (txh,tyh,tzh, txh,tyh,tzh, txl,tyl,tzl, 0...)
// giving q.t = hi.hi + lo.hi + hi.lo  (drops only lo.lo ~2^-22 rel).
// C-init carries -tsq/2, so D = q.t - tsq/2 and min_j d = qsq - 2*max_j D.
// ============================================================================
__global__ void __launch_bounds__(TPB)
chamfer_main(const float* __restrict__ adv, const float* __restrict__ ori) {
    // B pair-table interleaved so lane t LDS.64s (pair_t, pair_{t+4})
    __shared__ unsigned sB[SLICE][8];      // 32 KB
    __shared__ float2   sQ2[SLICE / 2];    // 4 KB  (-tsq/2 per target)
    __shared__ unsigned qA[QPB][8];        // 8 KB
    __shared__ float    sQsq[QPB];         // 1 KB

    int b   = blockIdx.x;
    int dir = b >= DIRBLKS;
    int rem = b - dir * DIRBLKS;
    int qt  = rem / TSPLIT;
    int sp  = rem % TSPLIT;
    int tid = threadIdx.x;

    const float* qsrc = dir ? ori : adv;
    const float* tsrc = dir ? adv : ori;
    const __half hz = __float2half_rn(0.f);

    // ---- stage target fragments (4 targets per thread) ----
#pragma unroll
    for (int k = 0; k < 4; k++) {
        int j  = tid + k * TPB;            // local target index
        int gj = sp * SLICE + j;           // global target index
        float x = tsrc[3 * gj + 0];
        float y = tsrc[3 * gj + 1];
        float z = tsrc[3 * gj + 2];
        __half xh = __float2half_rn(x), yh = __float2half_rn(y), zh = __float2half_rn(z);
        __half xl = __float2half_rn(x - __half2float(xh));
        __half yl = __float2half_rn(y - __half2float(yh));
        __half zl = __float2half_rn(z - __half2float(zh));
        // pairs by k-slot: Q0=(k0,k1) Q1=(k2,k3) Q2=(k4,k5) Q3=(k6,k7) Q4=(k8,k9)
        unsigned Q0 = pkh2(xh, yh), Q1 = pkh2(zh, xh), Q2 = pkh2(yh, zh);
        unsigned Q3 = pkh2(xl, yl), Q4 = pkh2(zl, hz);
        sB[j][0] = Q0; sB[j][1] = Q4;      // interleave: s[2p]=Q_p, s[2p+1]=Q_{p+4}
        sB[j][2] = Q1; sB[j][3] = 0u;
        sB[j][4] = Q2; sB[j][5] = 0u;
        sB[j][6] = Q3; sB[j][7] = 0u;
        reinterpret_cast<float*>(sQ2)[j] = -0.5f * (x * x + y * y + z * z);
    }

    // ---- stage query fragments (1 query per thread) ----
    {
        int gq = qt * QPB + tid;
        float x = qsrc[3 * gq + 0];
        float y = qsrc[3 * gq + 1];
        float z = qsrc[3 * gq + 2];
        __half xh = __float2half_rn(x), yh = __float2half_rn(y), zh = __float2half_rn(z);
        __half xl = __float2half_rn(x - __half2float(xh));
        __half yl = __float2half_rn(y - __half2float(yh));
        __half zl = __float2half_rn(z - __half2float(zh));
        // pairs: P0=(xh,yh) P1=(zh,xl) P2=(yl,zl) P3=(xh,yh) P4=(zh,0)
        unsigned P0 = pkh2(xh, yh), P1 = pkh2(zh, xl), P2 = pkh2(yl, zl);
        unsigned P3 = pkh2(xh, yh), P4 = pkh2(zh, hz);
        qA[tid][0] = P0; qA[tid][1] = P4;
        qA[tid][2] = P1; qA[tid][3] = 0u;
        qA[tid][4] = P2; qA[tid][5] = 0u;
        qA[tid][6] = P3; qA[tid][7] = 0u;
        sQsq[tid] = x * x + y * y + z * z;
    }
    __syncthreads();

    int lane = tid & 31;
    int warp = tid >> 5;
    int gid  = lane >> 2;   // 0..7
    int t    = lane & 3;    // 0..3
    int lr   = warp * 32 + gid;   // local query row for d0 of A-set 0

    // ---- A fragments (4 LDS.64, once) ----
    uint2 u0 = *reinterpret_cast<const uint2*>(&qA[lr +  0][2 * t]);
    uint2 u1 = *reinterpret_cast<const uint2*>(&qA[lr +  8][2 * t]);
    uint2 u2 = *reinterpret_cast<const uint2*>(&qA[lr + 16][2 * t]);
    uint2 u3 = *reinterpret_cast<const uint2*>(&qA[lr + 24][2 * t]);
    // set0: {a0,a1,a2,a3} = {A[gid][2t..], A[gid+8][2t..], A[gid][2t+8..], A[gid+8][2t+8..]}
    unsigned a00 = u0.x, a01 = u1.x, a02 = u0.y, a03 = u1.y;
    unsigned a10 = u2.x, a11 = u3.x, a12 = u2.y, a13 = u3.y;

    float ninf = __int_as_float(0xFF800000);
    float mx00 = ninf, mx01 = ninf, mx10 = ninf, mx11 = ninf;

#pragma unroll 4
    for (int j = 0; j < SLICE; j += 8) {
        int jj = j + gid;
        uint2  bb = *reinterpret_cast<const uint2*>(&sB[jj][2 * t]);
        float2 ci = sQ2[(j >> 1) + t];
        float d0, d1, d2, d3;
        MMA_F16(d0, d1, d2, d3, a00, a01, a02, a03, bb.x, bb.y, ci.x, ci.y, ci.x, ci.y);
        mx00 = fmaxf(mx00, fmaxf(d0, d1));
        mx01 = fmaxf(mx01, fmaxf(d2, d3));
        MMA_F16(d0, d1, d2, d3, a10, a11, a12, a13, bb.x, bb.y, ci.x, ci.y, ci.x, ci.y);
        mx10 = fmaxf(mx10, fmaxf(d0, d1));
        mx11 = fmaxf(mx11, fmaxf(d2, d3));
    }

    // ---- fold across the 4 t-lanes of each row, write slice partials ----
    unsigned m = 0xffffffffu;
#pragma unroll
    for (int s = 1; s <= 2; s <<= 1) {
        mx00 = fmaxf(mx00, __shfl_xor_sync(m, mx00, s));
        mx01 = fmaxf(mx01, __shfl_xor_sync(m, mx01, s));
        mx10 = fmaxf(mx10, __shfl_xor_sync(m, mx10, s));
        mx11 = fmaxf(mx11, __shfl_xor_sync(m, mx11, s));
    }
    if (t == 0) {
        int row = qt * QPB + lr;
        g_part[dir][sp][row +  0] = fmaf(-2.f, mx00, sQsq[lr +  0]);
        g_part[dir][sp][row +  8] = fmaf(-2.f, mx01, sQsq[lr +  8]);
        g_part[dir][sp][row + 16] = fmaf(-2.f, mx10, sQsq[lr + 16]);
        g_part[dir][sp][row + 24] = fmaf(-2.f, mx11, sQsq[lr + 24]);
    }
}

// ============================================================================
// Reduction stage A: fold the TSPLIT slice-partials per row, block-sum.
// ============================================================================
__global__ void __launch_bounds__(TPB)
chamfer_reduce_a() {
    __shared__ float sh[TPB];
    int rid = blockIdx.x * TPB + threadIdx.x;   // 0 .. 2*NPTS-1
    int dir = rid >> 14;
    int row = rid & (NPTS - 1);
    float mn = g_part[dir][0][row];
#pragma unroll
    for (int sp = 1; sp < TSPLIT; sp++) mn = fminf(mn, g_part[dir][sp][row]);
    sh[threadIdx.x] = mn;
    __syncthreads();
    for (int k = TPB / 2; k > 0; k >>= 1) {
        if (threadIdx.x < k) sh[threadIdx.x] += sh[threadIdx.x + k];
        __syncthreads();
    }
    if (threadIdx.x == 0) g_bsum[blockIdx.x] = sh[0];
}

// ============================================================================
// Reduction stage B: sum 128 block sums -> chamfer scalar.
// ============================================================================
__global__ void chamfer_reduce_b(float* __restrict__ out) {
    __shared__ float sh[REDA];
    sh[threadIdx.x] = g_bsum[threadIdx.x];
    __syncthreads();
    for (int k = REDA / 2; k > 0; k >>= 1) {
        if (threadIdx.x < k) sh[threadIdx.x] += sh[threadIdx.x + k];
        __syncthreads();
    }
    if (threadIdx.x == 0) out[0] = sh[0] / (float)NPTS;
}

extern "C" void kernel_launch(void* const* d_in, const int* in_sizes, int n_in,
                              void* d_out, int out_size) {
    const float* adv = (const float*)d_in[0];
    const float* ori = (const float*)d_in[1];
    chamfer_main<<<2 * DIRBLKS, TPB>>>(adv, ori);
    chamfer_reduce_a<<<REDA, TPB>>>();
    chamfer_reduce_b<<<1, REDA>>>((float*)d_out);
}